// round 11
// baseline (speedup 1.0000x reference)
#include <cuda_runtime.h>
#include <cstdint>

#define NRAY 131072
#define NINT 768

// Clamped-border images: rounded indices clamped to [-1, 512]; array row r
// holds logical index r-1, rows/cols 0 and 513 are the zero border, so any
// OOB midpoint reads 0 -> contributes 0 (matches reference masking).
// __device__ BSS is zero-initialized; borders are never written.
#define PDIM    514
#define PSTRIDE 516

__device__ float g_img [PDIM * PSTRIDE];   // [row][col]
__device__ float g_imgT[PDIM * PSTRIDE];   // [col][row]

__global__ void copy_img_kernel(const float* __restrict__ img) {
    int i = blockIdx.x * blockDim.x + threadIdx.x;   // 262,144 threads
    int r = i >> 9;
    int c = i & 511;
    float v = img[i];
    g_img [(r + 1) * PSTRIDE + (c + 1)] = v;
    g_imgT[(c + 1) * PSTRIDE + (r + 1)] = v;
}

#define MAGICF 12582912.0f      /* 2^23+2^22: fadd == rint (round-half-even) */
#define UMINB  0x4B3FFFFFu      /* bits of MAGICF + (-1)  -> clamped row 0   */
#define UMAXB  0x4B400200u      /* bits of MAGICF + 512   -> clamped row 513 */
#define KC     (UMINB * (unsigned)PSTRIDE + UMINB)   /* uint32 wrap, exact   */

// Fast path: M == I, b == 0 (runtime-verified). u = slow index (xPSTRIDE),
// v = fast index, pre-swapped so the dominant direction is contiguous.
// Index chain mirrors the reference op-for-op (scalar round-per-op; the
// FFMA fuses only an exact multiply-by-0.5 -- validated bit-exact R9/R10).
//
// float2 pairing: lane l owns segments 64j+2l and 64j+2l+1. The shared
// endpoint t[64j+2l+1] is computed ONCE and used as seg-A's far and
// seg-B's near endpoint (bit-identical chain either way). Per 64 segments:
// one 8B t-load, two shuffles, three endpoint evaluations per lane.
__device__ __forceinline__ float ray_loop_ident(
    const float* __restrict__ tp, int lane,
    float su, float du, float sv, float dv,
    const float* __restrict__ base)
{
    const unsigned full = 0xffffffffu;
    const float2* tp2 = reinterpret_cast<const float2*>(tp);  // 8B-aligned
    float acc = 0.0f;

    float2 r[4];                         // chunks j..j+3 resident (64 t each)
    #pragma unroll
    for (int k = 0; k < 4; ++k)
        r[k] = __ldcs(&tp2[32 * k + lane]);

    #pragma unroll
    for (int j = 0; j < 12; ++j) {
        float2 cur = r[j & 3];
        float2 ld = make_float2(0.f, 0.f);
        if (j < 8) ld = __ldcs(&tp2[32 * (j + 4) + lane]);   // prefetch j+4

        // Warp-uniform shuffles; per-lane select afterwards.
        float tfirst = __shfl_sync(full, r[(j + 1) & 3].x, 0); // t[64(j+1)]
        float tc     = __shfl_down_sync(full, cur.x, 1);       // t[64j+2l+2]
        if (lane == 31)
            tc = (j < 11) ? tfirst : cur.y;  // j==11: dt=0 -> exact 0 contrib

        // Three endpoints per lane (middle one shared by both segments).
        float xu0 = __fadd_rn(su, __fmul_rn(cur.x, du));
        float xv0 = __fadd_rn(sv, __fmul_rn(cur.x, dv));
        float xu1 = __fadd_rn(su, __fmul_rn(cur.y, du));
        float xv1 = __fadd_rn(sv, __fmul_rn(cur.y, dv));
        float xu2 = __fadd_rn(su, __fmul_rn(tc,    du));
        float xv2 = __fadd_rn(sv, __fmul_rn(tc,    dv));

        // Segment A: [cur.x, cur.y]
        unsigned ua = __float_as_uint(__fmaf_rn(__fadd_rn(xu0, xu1), 0.5f, MAGICF));
        unsigned va = __float_as_uint(__fmaf_rn(__fadd_rn(xv0, xv1), 0.5f, MAGICF));
        ua = umin(umax(ua, UMINB), UMAXB);
        va = umin(umax(va, UMINB), UMAXB);
        float pa = __ldg(base + (int)(ua * (unsigned)PSTRIDE + va - KC));
        acc = fmaf(pa, __fsub_rn(cur.y, cur.x), acc);

        // Segment B: [cur.y, tc]
        unsigned ub = __float_as_uint(__fmaf_rn(__fadd_rn(xu1, xu2), 0.5f, MAGICF));
        unsigned vb = __float_as_uint(__fmaf_rn(__fadd_rn(xv1, xv2), 0.5f, MAGICF));
        ub = umin(umax(ub, UMINB), UMAXB);
        vb = umin(umax(vb, UMINB), UMAXB);
        float pb = __ldg(base + (int)(ub * (unsigned)PSTRIDE + vb - KC));
        acc = fmaf(pb, __fsub_rn(tc, cur.y), acc);

        if (j < 8) r[j & 3] = ld;
    }
    return acc;
}

// General path (cold for this dataset): arbitrary M, b; same pairing,
// full reference chain (separate 0.5-mul, b-subtract, matrix) per segment.
__device__ __forceinline__ float ray_loop_gen(
    const float* __restrict__ tp, int lane,
    float sx, float dx, float sy, float dy, float b0, float b1,
    float cu0, float cu1, float cv0, float cv1,
    const float* __restrict__ base)
{
    const unsigned full = 0xffffffffu;
    const float2* tp2 = reinterpret_cast<const float2*>(tp);
    float acc = 0.0f;

    float2 r[4];
    #pragma unroll
    for (int k = 0; k < 4; ++k)
        r[k] = __ldcs(&tp2[32 * k + lane]);

    #pragma unroll
    for (int j = 0; j < 12; ++j) {
        float2 cur = r[j & 3];
        float2 ld = make_float2(0.f, 0.f);
        if (j < 8) ld = __ldcs(&tp2[32 * (j + 4) + lane]);

        float tfirst = __shfl_sync(full, r[(j + 1) & 3].x, 0);
        float tc     = __shfl_down_sync(full, cur.x, 1);
        if (lane == 31)
            tc = (j < 11) ? tfirst : cur.y;

        float x0 = __fadd_rn(sx, __fmul_rn(cur.x, dx));
        float y0 = __fadd_rn(sy, __fmul_rn(cur.x, dy));
        float x1 = __fadd_rn(sx, __fmul_rn(cur.y, dx));
        float y1 = __fadd_rn(sy, __fmul_rn(cur.y, dy));
        float x2 = __fadd_rn(sx, __fmul_rn(tc,    dx));
        float y2 = __fadd_rn(sy, __fmul_rn(tc,    dy));

        {   // Segment A
            float mx = __fsub_rn(__fmul_rn(0.5f, __fadd_rn(x0, x1)), b0);
            float my = __fsub_rn(__fmul_rn(0.5f, __fadd_rn(y0, y1)), b1);
            float uf = __fadd_rn(__fmul_rn(cu0, mx), __fmul_rn(cu1, my));
            float vf = __fadd_rn(__fmul_rn(cv0, mx), __fmul_rn(cv1, my));
            unsigned ub_ = __float_as_uint(__fadd_rn(uf, MAGICF));
            unsigned vb_ = __float_as_uint(__fadd_rn(vf, MAGICF));
            ub_ = umin(umax(ub_, UMINB), UMAXB);
            vb_ = umin(umax(vb_, UMINB), UMAXB);
            float pix = __ldg(base + (int)(ub_ * (unsigned)PSTRIDE + vb_ - KC));
            acc = fmaf(pix, __fsub_rn(cur.y, cur.x), acc);
        }
        {   // Segment B
            float mx = __fsub_rn(__fmul_rn(0.5f, __fadd_rn(x1, x2)), b0);
            float my = __fsub_rn(__fmul_rn(0.5f, __fadd_rn(y1, y2)), b1);
            float uf = __fadd_rn(__fmul_rn(cu0, mx), __fmul_rn(cu1, my));
            float vf = __fadd_rn(__fmul_rn(cv0, mx), __fmul_rn(cv1, my));
            unsigned ub_ = __float_as_uint(__fadd_rn(uf, MAGICF));
            unsigned vb_ = __float_as_uint(__fadd_rn(vf, MAGICF));
            ub_ = umin(umax(ub_, UMINB), UMAXB);
            vb_ = umin(umax(vb_, UMINB), UMAXB);
            float pix = __ldg(base + (int)(ub_ * (unsigned)PSTRIDE + vb_ - KC));
            acc = fmaf(pix, __fsub_rn(tc, cur.y), acc);
        }

        if (j < 8) r[j & 3] = ld;
    }
    return acc;
}

__global__ __launch_bounds__(256) void ct_kernel(
    const float* __restrict__ t_sorted,
    const float* __restrict__ Mm,
    const float* __restrict__ bb,
    const float* __restrict__ src,
    const float* __restrict__ dst,
    float* __restrict__ out)
{
    const unsigned full = 0xffffffffu;
    int ray  = (blockIdx.x * blockDim.x + threadIdx.x) >> 5;   // warp per ray
    int lane = threadIdx.x & 31;

    float m00 = Mm[0], m01 = Mm[1], m10 = Mm[2], m11 = Mm[3];
    float invdet = 1.0f / (m00 * m11 - m01 * m10);
    float i00 =  m11 * invdet, i01 = -m01 * invdet;
    float i10 = -m10 * invdet, i11 =  m00 * invdet;
    float b0 = bb[0], b1 = bb[1];
    bool ident = (i00 == 1.0f) & (i01 == 0.0f) & (i10 == 0.0f) &
                 (i11 == 1.0f) & (b0 == 0.0f) & (b1 == 0.0f);

    float sx = src[2 * ray],                sy = src[2 * ray + 1];
    float dx = __fsub_rn(dst[2 * ray], sx);
    float dy = __fsub_rn(dst[2 * ray + 1], sy);
    float L  = sqrtf(dx * dx + dy * dy);    // one sqrt per ray (len = dt*L)

    // Faster-varying index should be the contiguous (v) coordinate.
    float r_rate = fabsf(i00 * dx + i01 * dy);
    float c_rate = fabsf(i10 * dx + i11 * dy);
    bool trans = (r_rate > c_rate);         // row varies fast -> transposed

    const float* base = trans ? g_imgT : g_img;
    const float* tp = t_sorted + (size_t)ray * NINT;

    float acc;
    if (ident) {
        float su = trans ? sy : sx, du = trans ? dy : dx;
        float sv = trans ? sx : sy, dv = trans ? dx : dy;
        acc = ray_loop_ident(tp, lane, su, du, sv, dv, base);
    } else {
        float cu0 = trans ? i10 : i00, cu1 = trans ? i11 : i01;
        float cv0 = trans ? i00 : i10, cv1 = trans ? i01 : i11;
        acc = ray_loop_gen(tp, lane, sx, dx, sy, dy, b0, b1,
                           cu0, cu1, cv0, cv1, base);
    }

    #pragma unroll
    for (int s = 16; s > 0; s >>= 1)
        acc += __shfl_xor_sync(full, acc, s);

    if (lane == 0) out[ray] = acc * L;
}

extern "C" void kernel_launch(void* const* d_in, const int* in_sizes, int n_in,
                              void* d_out, int out_size)
{
    const float* image    = (const float*)d_in[0];
    const float* t_sorted = (const float*)d_in[1];
    const float* M        = (const float*)d_in[2];
    const float* b        = (const float*)d_in[3];
    const float* src      = (const float*)d_in[4];
    const float* dst      = (const float*)d_in[5];
    float* out = (float*)d_out;

    copy_img_kernel<<<1024, 256>>>(image);
    ct_kernel<<<NRAY / 8, 256>>>(t_sorted, M, b, src, dst, out);
}

// round 12
// speedup vs baseline: 1.1321x; 1.1321x over previous
#include <cuda_runtime.h>
#include <cstdint>

#define NRAY 131072
#define NINT 768

// Clamped-border images: rounded indices clamped to [-1, 512]; array row r
// holds logical index r-1, rows/cols 0 and 513 are the zero border, so any
// OOB midpoint reads 0 -> contributes 0 (matches reference masking).
// __device__ BSS is zero-initialized; borders are never written.
#define PDIM    514
#define PSTRIDE 516

__device__ float g_img [PDIM * PSTRIDE];   // [row][col]
__device__ float g_imgT[PDIM * PSTRIDE];   // [col][row]

__global__ void copy_img_kernel(const float* __restrict__ img) {
    int i = blockIdx.x * blockDim.x + threadIdx.x;   // 262,144 threads
    int r = i >> 9;
    int c = i & 511;
    float v = img[i];
    g_img [(r + 1) * PSTRIDE + (c + 1)] = v;
    g_imgT[(c + 1) * PSTRIDE + (r + 1)] = v;
}

#define MAGICF 12582912.0f      /* 2^23+2^22: fadd == rint (round-half-even) */
#define UMINB  0x4B3FFFFFu      /* bits of MAGICF + (-1)  -> clamped row 0   */
#define UMAXB  0x4B400200u      /* bits of MAGICF + 512   -> clamped row 513 */
#define KC     (UMINB * (unsigned)PSTRIDE + UMINB)   /* uint32 wrap, exact   */

// Conservative OOB window bounds (index units). The fp index chain deviates
// from real-valued u(t) by <= ~5e-4, so real u < -0.51 or > 511.51 PROVES
// the rounded index is OOB -> contribution exactly 0. (Validated in R9:
// identical rel_err with and without windowing.)
#define LO_G (-0.51f)
#define HI_G (511.51f)

// Fast path: M == I, b == 0 (runtime-verified). u = slow index (xPSTRIDE),
// v = fast index, pre-swapped so the dominant direction is contiguous.
// Index chain mirrors the reference op-for-op (scalar round-per-op; FFMA
// fuses only an exact multiply-by-0.5 -- validated bit-exact R9/R10).
// Loop body is exactly R8's proven structure; chunks wholly outside the
// in-bounds t-window are skipped by a DYNAMIC loop over [ja, jb] with
// explicit scalar ring rotation (no arrays -> no spills, no per-section
// guards -> none of R9's ALU bloat).
__device__ __forceinline__ float ray_loop_ident(
    const float* __restrict__ tp, int lane,
    float su, float du, float sv, float dv,
    const float* __restrict__ base)
{
    const unsigned full = 0xffffffffu;

    // ---- in-bounds t-window (warp-uniform) ----
    float tA = (LO_G - su) / du, tB = (HI_G - su) / du;
    float lou = fminf(tA, tB), hiu = fmaxf(tA, tB);
    if (isnan(tA) || isnan(tB)) { lou = -1e30f; hiu = 1e30f; }
    float tC = (LO_G - sv) / dv, tD = (HI_G - sv) / dv;
    float lov = fminf(tC, tD), hiv = fmaxf(tC, tD);
    if (isnan(tC) || isnan(tD)) { lov = -1e30f; hiv = 1e30f; }
    float wlo = fmaxf(lou, lov), whi = fminf(hiu, hiv);

    // ---- prepass: lane j<24 holds t[32j]; lanes >=24 hold t[767] ----
    int off = (lane < 24) ? (lane << 5) : 767;
    float s = __ldg(tp + off);
    float snext = __shfl_down_sync(full, s, 1);
    bool act = (lane < 24) && (snext >= wlo) && (s <= whi);
    unsigned mask = __ballot_sync(full, act);
    if (mask == 0u) return 0.0f;            // ray misses the image entirely
    int ja = __ffs(mask) - 1;
    int jb = 31 - __clz(mask);              // active chunks [ja, jb], contiguous
    // boundary t for chunk jb's lane-31 segment; jb==23 -> t[767] == own t0
    // -> dt = 0 -> phantom segment contributes exactly 0.
    float sA = __shfl_sync(full, s, jb + 1);

    // ---- prologue: chunks ja..ja+3 (clamped addresses; extras unused) ----
    float c0 = __ldcs(tp + (min(ja + 0, 23) << 5) + lane);
    float c1 = __ldcs(tp + (min(ja + 1, 23) << 5) + lane);
    float c2 = __ldcs(tp + (min(ja + 2, 23) << 5) + lane);
    float c3 = __ldcs(tp + (min(ja + 3, 23) << 5) + lane);

    float acc = 0.0f;
    #pragma unroll 4
    for (int j = ja; j <= jb; ++j) {
        float t0 = c0;
        float tnew = 0.0f;
        if (j + 4 <= jb) tnew = __ldcs(tp + ((j + 4) << 5) + lane);

        // Warp-uniform shuffles; per-lane select afterwards.
        float tfirst = __shfl_sync(full, c1, 0);      // next chunk's t[0]
        float tn     = __shfl_down_sync(full, t0, 1);
        if (lane == 31) tn = (j < jb) ? tfirst : sA;

        float xu0 = __fadd_rn(su, __fmul_rn(t0, du));
        float xv0 = __fadd_rn(sv, __fmul_rn(t0, dv));
        float xu1 = __fadd_rn(su, __fmul_rn(tn, du));
        float xv1 = __fadd_rn(sv, __fmul_rn(tn, dv));
        // 0.5*w exact -> FFMA == fmul(0.5)+fadd(magic), bit-identical
        unsigned ub = __float_as_uint(__fmaf_rn(__fadd_rn(xu0, xu1), 0.5f, MAGICF));
        unsigned vb = __float_as_uint(__fmaf_rn(__fadd_rn(xv0, xv1), 0.5f, MAGICF));
        ub = umin(umax(ub, UMINB), UMAXB);   // clamp index to [-1, 512]
        vb = umin(umax(vb, UMINB), UMAXB);
        float pix = __ldg(base + (int)(ub * (unsigned)PSTRIDE + vb - KC));

        acc = fmaf(pix, __fsub_rn(tn, t0), acc);
        c0 = c1; c1 = c2; c2 = c3; c3 = tnew;   // scalar rotation (renamed)
    }
    return acc;
}

// General path (cold for this dataset): arbitrary M, b; R8's proven static
// loop, unchanged.
__device__ __forceinline__ float ray_loop_gen(
    const float* __restrict__ tp, int lane,
    float sx, float dx, float sy, float dy, float b0, float b1,
    float cu0, float cu1, float cv0, float cv1,
    const float* __restrict__ base)
{
    const unsigned full = 0xffffffffu;
    float acc = 0.0f;

    float buf[4];
    #pragma unroll
    for (int k = 0; k < 4; ++k)
        buf[k] = __ldcs(tp + 32 * k + lane);

    #pragma unroll
    for (int j = 0; j < 24; ++j) {
        float t0 = buf[j & 3];
        float tload = 0.0f;
        if (j < 20) tload = __ldcs(tp + 32 * (j + 4) + lane);

        float tfirst = __shfl_sync(full, buf[(j + 1) & 3], 0);
        float tn     = __shfl_down_sync(full, t0, 1);
        if (lane == 31)
            tn = (j < 23) ? tfirst : t0;

        float x0 = __fadd_rn(sx, __fmul_rn(t0, dx));
        float y0 = __fadd_rn(sy, __fmul_rn(t0, dy));
        float x1 = __fadd_rn(sx, __fmul_rn(tn, dx));
        float y1 = __fadd_rn(sy, __fmul_rn(tn, dy));

        float mx = __fsub_rn(__fmul_rn(0.5f, __fadd_rn(x0, x1)), b0);
        float my = __fsub_rn(__fmul_rn(0.5f, __fadd_rn(y0, y1)), b1);
        float uf = __fadd_rn(__fmul_rn(cu0, mx), __fmul_rn(cu1, my));
        float vf = __fadd_rn(__fmul_rn(cv0, mx), __fmul_rn(cv1, my));

        unsigned ub = __float_as_uint(__fadd_rn(uf, MAGICF));
        unsigned vb = __float_as_uint(__fadd_rn(vf, MAGICF));
        ub = umin(umax(ub, UMINB), UMAXB);
        vb = umin(umax(vb, UMINB), UMAXB);
        float pix = __ldg(base + (int)(ub * (unsigned)PSTRIDE + vb - KC));

        acc = fmaf(pix, __fsub_rn(tn, t0), acc);
        buf[j & 3] = tload;
    }
    return acc;
}

__global__ __launch_bounds__(256) void ct_kernel(
    const float* __restrict__ t_sorted,
    const float* __restrict__ Mm,
    const float* __restrict__ bb,
    const float* __restrict__ src,
    const float* __restrict__ dst,
    float* __restrict__ out)
{
    const unsigned full = 0xffffffffu;
    int ray  = (blockIdx.x * blockDim.x + threadIdx.x) >> 5;   // warp per ray
    int lane = threadIdx.x & 31;

    float m00 = Mm[0], m01 = Mm[1], m10 = Mm[2], m11 = Mm[3];
    float invdet = 1.0f / (m00 * m11 - m01 * m10);
    float i00 =  m11 * invdet, i01 = -m01 * invdet;
    float i10 = -m10 * invdet, i11 =  m00 * invdet;
    float b0 = bb[0], b1 = bb[1];
    bool ident = (i00 == 1.0f) & (i01 == 0.0f) & (i10 == 0.0f) &
                 (i11 == 1.0f) & (b0 == 0.0f) & (b1 == 0.0f);

    float sx = src[2 * ray],                sy = src[2 * ray + 1];
    float dx = __fsub_rn(dst[2 * ray], sx);
    float dy = __fsub_rn(dst[2 * ray + 1], sy);
    float L  = sqrtf(dx * dx + dy * dy);    // one sqrt per ray (len = dt*L)

    // Faster-varying index should be the contiguous (v) coordinate.
    float r_rate = fabsf(i00 * dx + i01 * dy);
    float c_rate = fabsf(i10 * dx + i11 * dy);
    bool trans = (r_rate > c_rate);         // row varies fast -> transposed

    const float* base = trans ? g_imgT : g_img;
    const float* tp = t_sorted + (size_t)ray * NINT;

    float acc;
    if (ident) {
        float su = trans ? sy : sx, du = trans ? dy : dx;
        float sv = trans ? sx : sy, dv = trans ? dx : dy;
        acc = ray_loop_ident(tp, lane, su, du, sv, dv, base);
    } else {
        float cu0 = trans ? i10 : i00, cu1 = trans ? i11 : i01;
        float cv0 = trans ? i00 : i10, cv1 = trans ? i01 : i11;
        acc = ray_loop_gen(tp, lane, sx, dx, sy, dy, b0, b1,
                           cu0, cu1, cv0, cv1, base);
    }

    #pragma unroll
    for (int s = 16; s > 0; s >>= 1)
        acc += __shfl_xor_sync(full, acc, s);

    if (lane == 0) out[ray] = acc * L;
}

extern "C" void kernel_launch(void* const* d_in, const int* in_sizes, int n_in,
                              void* d_out, int out_size)
{
    const float* image    = (const float*)d_in[0];
    const float* t_sorted = (const float*)d_in[1];
    const float* M        = (const float*)d_in[2];
    const float* b        = (const float*)d_in[3];
    const float* src      = (const float*)d_in[4];
    const float* dst      = (const float*)d_in[5];
    float* out = (float*)d_out;

    copy_img_kernel<<<1024, 256>>>(image);
    ct_kernel<<<NRAY / 8, 256>>>(t_sorted, M, b, src, dst, out);
}